// round 8
// baseline (speedup 1.0000x reference)
#include <cuda_runtime.h>

#define S_LEN   8192
#define DIM     64
#define WSZ     64
#define Q_TILE  128
#define KV_ROWS 256          // Q_TILE + 2*WSZ
#define THREADS 256
#define SMEM_BYTES (2 * KV_ROWS * DIM * 4)   // K + V fp32 tiles = 131072 B

// ---- packed f32x2 FMA (Blackwell; ptxas never auto-fuses this) ----
union F2U { float2 f; unsigned long long u; };
__device__ __forceinline__ float2 ffma2(float2 a, float2 b, float2 c) {
    F2U A, B, C, R; A.f = a; B.f = b; C.f = c;
    asm("fma.rn.f32x2 %0, %1, %2, %3;" : "=l"(R.u) : "l"(A.u), "l"(B.u), "l"(C.u));
    return R.f;
}
__device__ __forceinline__ float ex2(float x) {
    float r; asm("ex2.approx.ftz.f32 %0, %1;" : "=f"(r) : "f"(x)); return r;
}
__device__ __forceinline__ float2 lo2(float4 a) { return make_float2(a.x, a.y); }
__device__ __forceinline__ float2 hi2(float4 a) { return make_float2(a.z, a.w); }

__global__ void __launch_bounds__(THREADS, 1)
swa_kernel(const float* __restrict__ q, const float* __restrict__ k,
           const float* __restrict__ v, float* __restrict__ out)
{
    extern __shared__ float4 smem[];
    float4* Ks = smem;                   // [KV_ROWS][16] float4
    float4* Vs = smem + KV_ROWS * 16;

    const int tid = threadIdx.x;
    const int b   = blockIdx.x >> 6;               // 64 tiles per batch
    const int t0  = (blockIdx.x & 63) * Q_TILE;    // first query of tile

    // ---------- load K/V slab (rows t0-64 .. t0+191), zero-fill OOB ----------
    const float4* kg = (const float4*)(k + (size_t)b * S_LEN * DIM);
    const float4* vg = (const float4*)(v + (size_t)b * S_LEN * DIM);
    #pragma unroll
    for (int it = 0; it < (KV_ROWS * 16) / THREADS; ++it) {  // 16 iters
        int i    = tid + it * THREADS;
        int row  = i >> 4;
        int grow = t0 - WSZ + row;
        float4 kk = make_float4(0.f, 0.f, 0.f, 0.f);
        float4 vv = kk;
        if (grow >= 0 && grow < S_LEN) {
            kk = kg[grow * 16 + (i & 15)];
            vv = vg[grow * 16 + (i & 15)];
        }
        Ks[i] = kk; Vs[i] = vv;
    }

    // ---------- per-thread query registers ----------
    const int pl  = tid >> 2;         // pair index 0..63 -> queries 2pl, 2pl+1
    const int seg = tid & 3;          // dim segment: [seg*16, seg*16+16)
    const int qa  = t0 + 2 * pl;      // global query a (qb = qa+1)

    // fold softmax scale (1/8) and log2(e) into Q
    const float SC = 0.125f * 1.4426950408889634f;
    float2 qra[8], qrb[8];
    {
        const float2* ga = (const float2*)(q + ((size_t)b * S_LEN + qa)     * DIM + seg * 16);
        const float2* gb = (const float2*)(q + ((size_t)b * S_LEN + qa + 1) * DIM + seg * 16);
        #pragma unroll
        for (int i = 0; i < 8; ++i) {
            float2 ta = ga[i], tb = gb[i];
            qra[i] = make_float2(ta.x * SC, ta.y * SC);
            qrb[i] = make_float2(tb.x * SC, tb.y * SC);
        }
    }

    float2 oa[8], ob[8];
    #pragma unroll
    for (int i = 0; i < 8; ++i) { oa[i] = make_float2(0.f, 0.f); ob[i] = oa[i]; }
    float la = 0.f, lb = 0.f;

    __syncthreads();

    // ---------- warp-uniform absolute-key loop with broadcast smem reads ----------
    // smem row r holds key index (t0 - 64 + r). Query 2pl attends rows [2pl, 2pl+128].
    const int wid  = tid >> 5;
    const int gmin = WSZ - t0;                         // first globally valid row
    const int gmax = S_LEN - 1 + WSZ - t0;             // last  globally valid row
    int r_lo = 16 * wid;        if (r_lo < gmin) r_lo = gmin;
    int r_hi = 16 * wid + 143;  if (r_hi > gmax) r_hi = gmax;

    const int ra_lo = (2 * pl     > gmin) ? 2 * pl     : gmin;
    const int ra_hi = (2 * pl + 128 < gmax) ? 2 * pl + 128 : gmax;
    const int rb_lo = (2 * pl + 1 > gmin) ? 2 * pl + 1 : gmin;
    const int rb_hi = (2 * pl + 129 < gmax) ? 2 * pl + 129 : gmax;

    #pragma unroll 2
    for (int r = r_lo; r <= r_hi; ++r) {
        // LDS.128 loads, K and V both front-loaded so V latency overlaps the
        // score->shfl->ex2 dependency chain (~100 cyc).
        const float4* kr4 = &Ks[r * 16 + seg * 4];
        const float4* vr4 = &Vs[r * 16 + seg * 4];
        float4 kk4[4], vv4[4];
        #pragma unroll
        for (int i = 0; i < 4; ++i) { kk4[i] = kr4[i]; vv4[i] = vr4[i]; }

        // two independent 4-deep FFMA2 chains per query
        float2 aa0 = make_float2(0.f, 0.f), aa1 = aa0;
        float2 ab0 = aa0, ab1 = aa0;
        #pragma unroll
        for (int i = 0; i < 4; ++i) {
            float2 klo = lo2(kk4[i]), khi = hi2(kk4[i]);
            aa0 = ffma2(qra[2 * i],     klo, aa0);
            aa1 = ffma2(qra[2 * i + 1], khi, aa1);
            ab0 = ffma2(qrb[2 * i],     klo, ab0);
            ab1 = ffma2(qrb[2 * i + 1], khi, ab1);
        }
        float sa = (aa0.x + aa0.y) + (aa1.x + aa1.y);
        float sb = (ab0.x + ab0.y) + (ab1.x + ab1.y);
        // reduce across the 4 seg lanes (lanes pl*4 .. pl*4+3)
        sa += __shfl_xor_sync(0xffffffffu, sa, 1);
        sa += __shfl_xor_sync(0xffffffffu, sa, 2);
        sb += __shfl_xor_sync(0xffffffffu, sb, 1);
        sb += __shfl_xor_sync(0xffffffffu, sb, 2);

        float ea = (r >= ra_lo && r <= ra_hi) ? ex2(sa) : 0.f;
        float eb = (r >= rb_lo && r <= rb_hi) ? ex2(sb) : 0.f;
        la += ea; lb += eb;

        float2 ea2 = make_float2(ea, ea);
        float2 eb2 = make_float2(eb, eb);
        #pragma unroll
        for (int i = 0; i < 4; ++i) {
            float2 vlo = lo2(vv4[i]), vhi = hi2(vv4[i]);
            oa[2 * i]     = ffma2(ea2, vlo, oa[2 * i]);
            oa[2 * i + 1] = ffma2(ea2, vhi, oa[2 * i + 1]);
            ob[2 * i]     = ffma2(eb2, vlo, ob[2 * i]);
            ob[2 * i + 1] = ffma2(eb2, vhi, ob[2 * i + 1]);
        }
    }

    // ---------- epilogue ----------
    const float inva = 1.f / la;
    const float invb = 1.f / lb;
    float2* ga = (float2*)(out + ((size_t)b * S_LEN + qa)     * DIM + seg * 16);
    float2* gb = (float2*)(out + ((size_t)b * S_LEN + qa + 1) * DIM + seg * 16);
    #pragma unroll
    for (int i = 0; i < 8; ++i) {
        ga[i] = make_float2(oa[i].x * inva, oa[i].y * inva);
        gb[i] = make_float2(ob[i].x * invb, ob[i].y * invb);
    }
}

extern "C" void kernel_launch(void* const* d_in, const int* in_sizes, int n_in,
                              void* d_out, int out_size)
{
    (void)in_sizes; (void)n_in; (void)out_size;
    const float* q = (const float*)d_in[0];
    const float* k = (const float*)d_in[1];
    const float* v = (const float*)d_in[2];
    float* o       = (float*)d_out;

    cudaFuncSetAttribute(swa_kernel, cudaFuncAttributeMaxDynamicSharedMemorySize, SMEM_BYTES);
    // grid: 2 batches * 64 tiles = 128 CTAs (one wave on 148 SMs)
    swa_kernel<<<128, THREADS, SMEM_BYTES>>>(q, k, v, o);
}

// round 11
// speedup vs baseline: 1.2597x; 1.2597x over previous
#include <cuda_runtime.h>

#define S_LEN   8192
#define DIM     64
#define WSZ     64
#define Q_TILE  128
#define KV_ROWS 256          // Q_TILE + 2*WSZ
#define THREADS 256
#define SMEM_BYTES (2 * KV_ROWS * DIM * 4)   // K + V fp32 tiles = 131072 B

// ---- packed f32x2 FMA (Blackwell; ptxas never auto-fuses this) ----
union F2U { float2 f; unsigned long long u; };
__device__ __forceinline__ float2 ffma2(float2 a, float2 b, float2 c) {
    F2U A, B, C, R; A.f = a; B.f = b; C.f = c;
    asm("fma.rn.f32x2 %0, %1, %2, %3;" : "=l"(R.u) : "l"(A.u), "l"(B.u), "l"(C.u));
    return R.f;
}
__device__ __forceinline__ float ex2(float x) {
    float r; asm("ex2.approx.ftz.f32 %0, %1;" : "=f"(r) : "f"(x)); return r;
}
__device__ __forceinline__ float2 lo2(float4 a) { return make_float2(a.x, a.y); }
__device__ __forceinline__ float2 hi2(float4 a) { return make_float2(a.z, a.w); }

__global__ void __launch_bounds__(THREADS, 1)
swa_kernel(const float* __restrict__ q, const float* __restrict__ k,
           const float* __restrict__ v, float* __restrict__ out)
{
    extern __shared__ float4 smem[];
    float4* Ks = smem;                   // [KV_ROWS][16] float4
    float4* Vs = smem + KV_ROWS * 16;

    const int tid = threadIdx.x;
    const int b   = blockIdx.x >> 6;               // 64 tiles per batch
    const int t0  = (blockIdx.x & 63) * Q_TILE;    // first query of tile

    // ---------- load K/V slab (rows t0-64 .. t0+191), zero-fill OOB ----------
    const float4* kg = (const float4*)(k + (size_t)b * S_LEN * DIM);
    const float4* vg = (const float4*)(v + (size_t)b * S_LEN * DIM);
    #pragma unroll
    for (int it = 0; it < (KV_ROWS * 16) / THREADS; ++it) {  // 16 iters
        int i    = tid + it * THREADS;
        int row  = i >> 4;
        int grow = t0 - WSZ + row;
        float4 kk = make_float4(0.f, 0.f, 0.f, 0.f);
        float4 vv = kk;
        if (grow >= 0 && grow < S_LEN) {
            kk = kg[grow * 16 + (i & 15)];
            vv = vg[grow * 16 + (i & 15)];
        }
        Ks[i] = kk; Vs[i] = vv;
    }

    // ---------- thread mapping: warp-pair p covers 32 queries; halves split rows ----------
    const int wid  = tid >> 5, lane = tid & 31;
    const int p    = wid >> 1;          // query group 0..3 -> queries [32p, 32p+32)
    const int half = wid & 1;           // row-range half
    const int qg   = lane >> 2;         // 8 query sub-groups per warp
    const int seg  = lane & 3;          // dim segment [seg*16, seg*16+16)
    const int q0   = 32 * p + 4 * qg;   // this thread's first local query (handles q0..q0+3)

    // fold softmax scale (1/8) and log2(e) into Q
    const float SC = 0.125f * 1.4426950408889634f;
    float2 qr[4][8];
    #pragma unroll
    for (int j = 0; j < 4; ++j) {
        const float4* g = (const float4*)(q + ((size_t)b * S_LEN + t0 + q0 + j) * DIM + seg * 16);
        #pragma unroll
        for (int i = 0; i < 4; ++i) {
            float4 t = g[i];
            qr[j][2 * i]     = make_float2(t.x * SC, t.y * SC);
            qr[j][2 * i + 1] = make_float2(t.z * SC, t.w * SC);
        }
    }

    float2 o[4][8];
    float  l[4];
    #pragma unroll
    for (int j = 0; j < 4; ++j) {
        l[j] = 0.f;
        #pragma unroll
        for (int i = 0; i < 8; ++i) o[j][i] = make_float2(0.f, 0.f);
    }

    // smem row r holds key (t0-64+r); local query ql attends rows [ql, ql+128]
    const int gmin = WSZ - t0;
    const int gmax = S_LEN - 1 + WSZ - t0;
    int lo[4], hi[4];
    #pragma unroll
    for (int j = 0; j < 4; ++j) {
        int ql = q0 + j;
        lo[j] = (ql       > gmin) ? ql       : gmin;
        hi[j] = (ql + 128 < gmax) ? ql + 128 : gmax;
    }
    int r_lo = 32 * p + 80 * half;       if (r_lo < gmin) r_lo = gmin;
    int r_hi = 32 * p + 80 * half + 79;  if (r_hi > gmax) r_hi = gmax;

    __syncthreads();

    for (int r = r_lo; r <= r_hi; ++r) {
        const float4* kr4 = &Ks[r * 16 + seg * 4];
        const float4* vr4 = &Vs[r * 16 + seg * 4];
        float4 kk[4], vv[4];
        #pragma unroll
        for (int i = 0; i < 4; ++i) { kk[i] = kr4[i]; vv[i] = vr4[i]; }

        float2 s2[4];
        #pragma unroll
        for (int j = 0; j < 4; ++j) s2[j] = make_float2(0.f, 0.f);
        #pragma unroll
        for (int i = 0; i < 4; ++i) {
            float2 klo = lo2(kk[i]), khi = hi2(kk[i]);
            #pragma unroll
            for (int j = 0; j < 4; ++j) {
                s2[j] = ffma2(qr[j][2 * i],     klo, s2[j]);
                s2[j] = ffma2(qr[j][2 * i + 1], khi, s2[j]);
            }
        }

        float e[4];
        #pragma unroll
        for (int j = 0; j < 4; ++j) {
            float s = s2[j].x + s2[j].y;
            s += __shfl_xor_sync(0xffffffffu, s, 1);
            s += __shfl_xor_sync(0xffffffffu, s, 2);
            e[j] = (r >= lo[j] && r <= hi[j]) ? ex2(s) : 0.f;
            l[j] += e[j];
        }

        #pragma unroll
        for (int i = 0; i < 4; ++i) {
            float2 vlo = lo2(vv[i]), vhi = hi2(vv[i]);
            #pragma unroll
            for (int j = 0; j < 4; ++j) {
                float2 ee = make_float2(e[j], e[j]);
                o[j][2 * i]     = ffma2(ee, vlo, o[j][2 * i]);
                o[j][2 * i + 1] = ffma2(ee, vhi, o[j][2 * i + 1]);
            }
        }
    }

    // ---------- merge halves through smem (reuse Ks region as staging) ----------
    __syncthreads();                      // all warps done reading Ks/Vs
    float* stgo = (float*)smem;           // [Q_TILE][DIM] fp32 = 32 KB
    float* stgl = stgo + Q_TILE * DIM;    // [Q_TILE]

    if (half == 1) {
        #pragma unroll
        for (int j = 0; j < 4; ++j) {
            float4* dst = (float4*)(stgo + (q0 + j) * DIM + seg * 16);
            #pragma unroll
            for (int i = 0; i < 4; ++i)
                dst[i] = make_float4(o[j][2 * i].x,     o[j][2 * i].y,
                                     o[j][2 * i + 1].x, o[j][2 * i + 1].y);
            if (seg == 0) stgl[q0 + j] = l[j];
        }
    }
    __syncthreads();

    if (half == 0) {
        #pragma unroll
        for (int j = 0; j < 4; ++j) {
            float lt  = l[j] + stgl[q0 + j];
            float inv = 1.f / lt;
            const float4* src = (const float4*)(stgo + (q0 + j) * DIM + seg * 16);
            float4* dst = (float4*)(out + ((size_t)b * S_LEN + t0 + q0 + j) * DIM + seg * 16);
            #pragma unroll
            for (int i = 0; i < 4; ++i) {
                float4 t = src[i];
                dst[i] = make_float4((o[j][2 * i].x     + t.x) * inv,
                                     (o[j][2 * i].y     + t.y) * inv,
                                     (o[j][2 * i + 1].x + t.z) * inv,
                                     (o[j][2 * i + 1].y + t.w) * inv);
            }
        }
    }
}

extern "C" void kernel_launch(void* const* d_in, const int* in_sizes, int n_in,
                              void* d_out, int out_size)
{
    (void)in_sizes; (void)n_in; (void)out_size;
    const float* q = (const float*)d_in[0];
    const float* k = (const float*)d_in[1];
    const float* v = (const float*)d_in[2];
    float* o       = (float*)d_out;

    cudaFuncSetAttribute(swa_kernel, cudaFuncAttributeMaxDynamicSharedMemorySize, SMEM_BYTES);
    // grid: 2 batches * 64 tiles = 128 CTAs (one wave on 148 SMs)
    swa_kernel<<<128, THREADS, SMEM_BYTES>>>(q, k, v, o);
}

// round 12
// speedup vs baseline: 1.3969x; 1.1089x over previous
#include <cuda_runtime.h>

#define S_LEN   8192
#define DIM     64
#define WSZ     64
#define Q_TILE  128
#define KV_ROWS 256          // Q_TILE + 2*WSZ
#define THREADS 256
#define SMEM_BYTES (2 * KV_ROWS * DIM * 4)   // K + V fp32 tiles = 131072 B

// ---- packed f32x2 FMA (Blackwell; ptxas never auto-fuses this) ----
union F2U { float2 f; unsigned long long u; };
__device__ __forceinline__ float2 ffma2(float2 a, float2 b, float2 c) {
    F2U A, B, C, R; A.f = a; B.f = b; C.f = c;
    asm("fma.rn.f32x2 %0, %1, %2, %3;" : "=l"(R.u) : "l"(A.u), "l"(B.u), "l"(C.u));
    return R.f;
}
__device__ __forceinline__ float ex2(float x) {
    float r; asm("ex2.approx.ftz.f32 %0, %1;" : "=f"(r) : "f"(x)); return r;
}
__device__ __forceinline__ float2 lo2(float4 a) { return make_float2(a.x, a.y); }
__device__ __forceinline__ float2 hi2(float4 a) { return make_float2(a.z, a.w); }

__global__ void __launch_bounds__(THREADS, 1)
swa_kernel(const float* __restrict__ q, const float* __restrict__ k,
           const float* __restrict__ v, float* __restrict__ out)
{
    extern __shared__ float4 smem[];
    float4* Ks = smem;                   // [KV_ROWS][16] float4
    float4* Vs = smem + KV_ROWS * 16;

    const int tid = threadIdx.x;
    const int b   = blockIdx.x >> 6;               // 64 tiles per batch
    const int t0  = (blockIdx.x & 63) * Q_TILE;    // first query of tile

    // ---------- load K/V slab (rows t0-64 .. t0+191), zero-fill OOB ----------
    const float4* kg = (const float4*)(k + (size_t)b * S_LEN * DIM);
    const float4* vg = (const float4*)(v + (size_t)b * S_LEN * DIM);
    #pragma unroll
    for (int it = 0; it < (KV_ROWS * 16) / THREADS; ++it) {  // 16 iters
        int i    = tid + it * THREADS;
        int row  = i >> 4;
        int grow = t0 - WSZ + row;
        float4 kk = make_float4(0.f, 0.f, 0.f, 0.f);
        float4 vv = kk;
        if (grow >= 0 && grow < S_LEN) {
            kk = kg[grow * 16 + (i & 15)];
            vv = vg[grow * 16 + (i & 15)];
        }
        Ks[i] = kk; Vs[i] = vv;
    }

    // ---------- thread mapping: warp-pair p covers 32 queries; halves split rows ----------
    const int wid  = tid >> 5, lane = tid & 31;
    const int p    = wid >> 1;          // query group 0..3 -> queries [32p, 32p+32)
    const int half = wid & 1;           // row-range half
    const int qg   = lane >> 2;         // 8 query sub-groups per warp
    const int seg  = lane & 3;          // dim segment [seg*16, seg*16+16)
    const int q0   = 32 * p + 4 * qg;   // this thread's first local query (handles q0..q0+3)

    // fold softmax scale (1/8) and log2(e) into Q
    const float SC = 0.125f * 1.4426950408889634f;
    float2 qr[4][8];
    #pragma unroll
    for (int j = 0; j < 4; ++j) {
        const float4* g = (const float4*)(q + ((size_t)b * S_LEN + t0 + q0 + j) * DIM + seg * 16);
        #pragma unroll
        for (int i = 0; i < 4; ++i) {
            float4 t = g[i];
            qr[j][2 * i]     = make_float2(t.x * SC, t.y * SC);
            qr[j][2 * i + 1] = make_float2(t.z * SC, t.w * SC);
        }
    }

    float2 o[4][8];
    float  l[4];
    #pragma unroll
    for (int j = 0; j < 4; ++j) {
        l[j] = 0.f;
        #pragma unroll
        for (int i = 0; i < 8; ++i) o[j][i] = make_float2(0.f, 0.f);
    }

    // smem row r holds key (t0-64+r); local query ql attends rows [ql, ql+128]
    const int gmin = WSZ - t0;
    const int gmax = S_LEN - 1 + WSZ - t0;
    int lo[4], hi[4];
    #pragma unroll
    for (int j = 0; j < 4; ++j) {
        int ql = q0 + j;
        lo[j] = (ql       > gmin) ? ql       : gmin;
        hi[j] = (ql + 128 < gmax) ? ql + 128 : gmax;
    }
    int r_lo = 32 * p + 80 * half;       if (r_lo < gmin) r_lo = gmin;
    int r_hi = 32 * p + 80 * half + 79;  if (r_hi > gmax) r_hi = gmax;

    __syncthreads();

    // ---------- software-pipelined row loop: prefetch r+1 while computing r ----------
    float4 kk[4], vv[4];
    {   // prologue: load first row (r_lo <= r_hi always: self-row guarantees non-empty
        // union, and each 80-row half contains >= 1 valid row for all tiles)
        const float4* kr4 = &Ks[r_lo * 16 + seg * 4];
        const float4* vr4 = &Vs[r_lo * 16 + seg * 4];
        #pragma unroll
        for (int i = 0; i < 4; ++i) { kk[i] = kr4[i]; vv[i] = vr4[i]; }
    }

    #pragma unroll 2
    for (int r = r_lo; r <= r_hi; ++r) {
        // prefetch next row into B while A computes (peeled: last iter skips)
        float4 kkB[4], vvB[4];
        if (r < r_hi) {
            const float4* kr4 = &Ks[(r + 1) * 16 + seg * 4];
            const float4* vr4 = &Vs[(r + 1) * 16 + seg * 4];
            #pragma unroll
            for (int i = 0; i < 4; ++i) { kkB[i] = kr4[i]; vvB[i] = vr4[i]; }
        }

        float2 s2[4];
        #pragma unroll
        for (int j = 0; j < 4; ++j) s2[j] = make_float2(0.f, 0.f);
        #pragma unroll
        for (int i = 0; i < 4; ++i) {
            float2 klo = lo2(kk[i]), khi = hi2(kk[i]);
            #pragma unroll
            for (int j = 0; j < 4; ++j) {
                s2[j] = ffma2(qr[j][2 * i],     klo, s2[j]);
                s2[j] = ffma2(qr[j][2 * i + 1], khi, s2[j]);
            }
        }

        float e[4];
        #pragma unroll
        for (int j = 0; j < 4; ++j) {
            float s = s2[j].x + s2[j].y;
            s += __shfl_xor_sync(0xffffffffu, s, 1);
            s += __shfl_xor_sync(0xffffffffu, s, 2);
            e[j] = (r >= lo[j] && r <= hi[j]) ? ex2(s) : 0.f;
            l[j] += e[j];
        }

        #pragma unroll
        for (int i = 0; i < 4; ++i) {
            float2 vlo = lo2(vv[i]), vhi = hi2(vv[i]);
            #pragma unroll
            for (int j = 0; j < 4; ++j) {
                float2 ee = make_float2(e[j], e[j]);
                o[j][2 * i]     = ffma2(ee, vlo, o[j][2 * i]);
                o[j][2 * i + 1] = ffma2(ee, vhi, o[j][2 * i + 1]);
            }
        }

        // rotate pipeline (register renames, no real moves after scheduling)
        #pragma unroll
        for (int i = 0; i < 4; ++i) { kk[i] = kkB[i]; vv[i] = vvB[i]; }
    }

    // ---------- merge halves through smem (reuse Ks region as staging) ----------
    __syncthreads();                      // all warps done reading Ks/Vs
    float* stgo = (float*)smem;           // [Q_TILE][DIM] fp32 = 32 KB
    float* stgl = stgo + Q_TILE * DIM;    // [Q_TILE]

    if (half == 1) {
        #pragma unroll
        for (int j = 0; j < 4; ++j) {
            float4* dst = (float4*)(stgo + (q0 + j) * DIM + seg * 16);
            #pragma unroll
            for (int i = 0; i < 4; ++i)
                dst[i] = make_float4(o[j][2 * i].x,     o[j][2 * i].y,
                                     o[j][2 * i + 1].x, o[j][2 * i + 1].y);
            if (seg == 0) stgl[q0 + j] = l[j];
        }
    }
    __syncthreads();

    if (half == 0) {
        #pragma unroll
        for (int j = 0; j < 4; ++j) {
            float lt  = l[j] + stgl[q0 + j];
            float inv = 1.f / lt;
            const float4* src = (const float4*)(stgo + (q0 + j) * DIM + seg * 16);
            float4* dst = (float4*)(out + ((size_t)b * S_LEN + t0 + q0 + j) * DIM + seg * 16);
            #pragma unroll
            for (int i = 0; i < 4; ++i) {
                float4 t = src[i];
                dst[i] = make_float4((o[j][2 * i].x     + t.x) * inv,
                                     (o[j][2 * i].y     + t.y) * inv,
                                     (o[j][2 * i + 1].x + t.z) * inv,
                                     (o[j][2 * i + 1].y + t.w) * inv);
            }
        }
    }
}

extern "C" void kernel_launch(void* const* d_in, const int* in_sizes, int n_in,
                              void* d_out, int out_size)
{
    (void)in_sizes; (void)n_in; (void)out_size;
    const float* q = (const float*)d_in[0];
    const float* k = (const float*)d_in[1];
    const float* v = (const float*)d_in[2];
    float* o       = (float*)d_out;

    cudaFuncSetAttribute(swa_kernel, cudaFuncAttributeMaxDynamicSharedMemorySize, SMEM_BYTES);
    // grid: 2 batches * 64 tiles = 128 CTAs (one wave on 148 SMs)
    swa_kernel<<<128, THREADS, SMEM_BYTES>>>(q, k, v, o);
}

// round 16
// speedup vs baseline: 1.4058x; 1.0063x over previous
#include <cuda_runtime.h>

#define S_LEN   8192
#define DIM     64
#define WSZ     64
#define Q_TILE  128
#define KV_ROWS 256          // Q_TILE + 2*WSZ
#define THREADS 256
#define SMEM_BYTES (2 * KV_ROWS * DIM * 4)   // K + V fp32 tiles = 131072 B

// ---- packed f32x2 FMA (Blackwell; ptxas never auto-fuses this) ----
union F2U { float2 f; unsigned long long u; };
__device__ __forceinline__ float2 ffma2(float2 a, float2 b, float2 c) {
    F2U A, B, C, R; A.f = a; B.f = b; C.f = c;
    asm("fma.rn.f32x2 %0, %1, %2, %3;" : "=l"(R.u) : "l"(A.u), "l"(B.u), "l"(C.u));
    return R.f;
}
__device__ __forceinline__ float ex2(float x) {
    float r; asm("ex2.approx.ftz.f32 %0, %1;" : "=f"(r) : "f"(x)); return r;
}
__device__ __forceinline__ float2 lo2(float4 a) { return make_float2(a.x, a.y); }
__device__ __forceinline__ float2 hi2(float4 a) { return make_float2(a.z, a.w); }

// load row r's K/V slice (seg*16 .. seg*16+16 dims) into 4+4 float4 regs
#define LOAD_ROW(KK, VV, r) do {                                         \
    const float4* _kr = &Ks[(r) * 16 + seg * 4];                         \
    const float4* _vr = &Vs[(r) * 16 + seg * 4];                         \
    _Pragma("unroll")                                                    \
    for (int _i = 0; _i < 4; ++_i) { (KK)[_i] = _kr[_i]; (VV)[_i] = _vr[_i]; } \
} while (0)

// full per-row body on buffer (KK, VV) for row r
#define COMPUTE_ROW(KK, VV, r) do {                                      \
    float2 _s2[4];                                                       \
    _Pragma("unroll")                                                    \
    for (int _j = 0; _j < 4; ++_j) _s2[_j] = make_float2(0.f, 0.f);      \
    _Pragma("unroll")                                                    \
    for (int _i = 0; _i < 4; ++_i) {                                     \
        float2 _klo = lo2((KK)[_i]), _khi = hi2((KK)[_i]);               \
        _Pragma("unroll")                                                \
        for (int _j = 0; _j < 4; ++_j) {                                 \
            _s2[_j] = ffma2(qr[_j][2 * _i],     _klo, _s2[_j]);          \
            _s2[_j] = ffma2(qr[_j][2 * _i + 1], _khi, _s2[_j]);          \
        }                                                                \
    }                                                                    \
    float _e[4];                                                         \
    _Pragma("unroll")                                                    \
    for (int _j = 0; _j < 4; ++_j) {                                     \
        float _s = _s2[_j].x + _s2[_j].y;                                \
        _s += __shfl_xor_sync(0xffffffffu, _s, 1);                       \
        _s += __shfl_xor_sync(0xffffffffu, _s, 2);                       \
        _e[_j] = ((r) >= lo[_j] && (r) <= hi[_j]) ? ex2(_s) : 0.f;       \
        l[_j] += _e[_j];                                                 \
    }                                                                    \
    _Pragma("unroll")                                                    \
    for (int _i = 0; _i < 4; ++_i) {                                     \
        float2 _vlo = lo2((VV)[_i]), _vhi = hi2((VV)[_i]);               \
        _Pragma("unroll")                                                \
        for (int _j = 0; _j < 4; ++_j) {                                 \
            float2 _ee = make_float2(_e[_j], _e[_j]);                    \
            o[_j][2 * _i]     = ffma2(_ee, _vlo, o[_j][2 * _i]);         \
            o[_j][2 * _i + 1] = ffma2(_ee, _vhi, o[_j][2 * _i + 1]);     \
        }                                                                \
    }                                                                    \
} while (0)

__global__ void __launch_bounds__(THREADS, 1)
swa_kernel(const float* __restrict__ q, const float* __restrict__ k,
           const float* __restrict__ v, float* __restrict__ out)
{
    extern __shared__ float4 smem[];
    float4* Ks = smem;                   // [KV_ROWS][16] float4
    float4* Vs = smem + KV_ROWS * 16;

    const int tid = threadIdx.x;
    const int b   = blockIdx.x >> 6;               // 64 tiles per batch
    const int t0  = (blockIdx.x & 63) * Q_TILE;    // first query of tile

    // ---------- load K/V slab (rows t0-64 .. t0+191), zero-fill OOB ----------
    const float4* kg = (const float4*)(k + (size_t)b * S_LEN * DIM);
    const float4* vg = (const float4*)(v + (size_t)b * S_LEN * DIM);
    #pragma unroll
    for (int it = 0; it < (KV_ROWS * 16) / THREADS; ++it) {  // 16 iters
        int i    = tid + it * THREADS;
        int row  = i >> 4;
        int grow = t0 - WSZ + row;
        float4 kk = make_float4(0.f, 0.f, 0.f, 0.f);
        float4 vv = kk;
        if (grow >= 0 && grow < S_LEN) {
            kk = kg[grow * 16 + (i & 15)];
            vv = vg[grow * 16 + (i & 15)];
        }
        Ks[i] = kk; Vs[i] = vv;
    }

    // ---------- thread mapping: warp-pair p covers 32 queries; halves split rows ----------
    const int wid  = tid >> 5, lane = tid & 31;
    const int p    = wid >> 1;          // query group 0..3 -> queries [32p, 32p+32)
    const int half = wid & 1;           // row-range half
    const int qg   = lane >> 2;         // 8 query sub-groups per warp
    const int seg  = lane & 3;          // dim segment [seg*16, seg*16+16)
    const int q0   = 32 * p + 4 * qg;   // this thread's first local query (handles q0..q0+3)

    // fold softmax scale (1/8) and log2(e) into Q
    const float SC = 0.125f * 1.4426950408889634f;
    float2 qr[4][8];
    #pragma unroll
    for (int j = 0; j < 4; ++j) {
        const float4* g = (const float4*)(q + ((size_t)b * S_LEN + t0 + q0 + j) * DIM + seg * 16);
        #pragma unroll
        for (int i = 0; i < 4; ++i) {
            float4 t = g[i];
            qr[j][2 * i]     = make_float2(t.x * SC, t.y * SC);
            qr[j][2 * i + 1] = make_float2(t.z * SC, t.w * SC);
        }
    }

    float2 o[4][8];
    float  l[4];
    #pragma unroll
    for (int j = 0; j < 4; ++j) {
        l[j] = 0.f;
        #pragma unroll
        for (int i = 0; i < 8; ++i) o[j][i] = make_float2(0.f, 0.f);
    }

    // smem row r holds key (t0-64+r); local query ql attends rows [ql, ql+128]
    const int gmin = WSZ - t0;
    const int gmax = S_LEN - 1 + WSZ - t0;
    int lo[4], hi[4];
    #pragma unroll
    for (int j = 0; j < 4; ++j) {
        int ql = q0 + j;
        lo[j] = (ql       > gmin) ? ql       : gmin;
        hi[j] = (ql + 128 < gmax) ? ql + 128 : gmax;
    }
    int r_lo = 32 * p + 80 * half;       if (r_lo < gmin) r_lo = gmin;
    int r_hi = 32 * p + 80 * half + 79;  if (r_hi > gmax) r_hi = gmax;

    __syncthreads();

    // ---------- phase-alternating double-buffered row loop (no rotation copies) ----------
    float4 kA[4], vA[4], kB[4], vB[4];
    LOAD_ROW(kA, vA, r_lo);
    int r = r_lo;
    for (; r + 1 <= r_hi; r += 2) {
        LOAD_ROW(kB, vB, r + 1);         // prefetch row r+1 while computing r
        COMPUTE_ROW(kA, vA, r);
        if (r + 2 <= r_hi) LOAD_ROW(kA, vA, r + 2);   // prefetch r+2 while computing r+1
        COMPUTE_ROW(kB, vB, r + 1);
    }
    if (r <= r_hi) {                     // odd remainder: kA/vA hold row r
        COMPUTE_ROW(kA, vA, r);
    }

    // ---------- merge halves through smem (reuse Ks region as staging) ----------
    __syncthreads();                      // all warps done reading Ks/Vs
    float* stgo = (float*)smem;           // [Q_TILE][DIM] fp32 = 32 KB
    float* stgl = stgo + Q_TILE * DIM;    // [Q_TILE]

    if (half == 1) {
        #pragma unroll
        for (int j = 0; j < 4; ++j) {
            float4* dst = (float4*)(stgo + (q0 + j) * DIM + seg * 16);
            #pragma unroll
            for (int i = 0; i < 4; ++i)
                dst[i] = make_float4(o[j][2 * i].x,     o[j][2 * i].y,
                                     o[j][2 * i + 1].x, o[j][2 * i + 1].y);
            if (seg == 0) stgl[q0 + j] = l[j];
        }
    }
    __syncthreads();

    if (half == 0) {
        #pragma unroll
        for (int j = 0; j < 4; ++j) {
            float lt  = l[j] + stgl[q0 + j];
            float inv = 1.f / lt;
            const float4* src = (const float4*)(stgo + (q0 + j) * DIM + seg * 16);
            float4* dst = (float4*)(out + ((size_t)b * S_LEN + t0 + q0 + j) * DIM + seg * 16);
            #pragma unroll
            for (int i = 0; i < 4; ++i) {
                float4 t = src[i];
                dst[i] = make_float4((o[j][2 * i].x     + t.x) * inv,
                                     (o[j][2 * i].y     + t.y) * inv,
                                     (o[j][2 * i + 1].x + t.z) * inv,
                                     (o[j][2 * i + 1].y + t.w) * inv);
            }
        }
    }
}

extern "C" void kernel_launch(void* const* d_in, const int* in_sizes, int n_in,
                              void* d_out, int out_size)
{
    (void)in_sizes; (void)n_in; (void)out_size;
    const float* q = (const float*)d_in[0];
    const float* k = (const float*)d_in[1];
    const float* v = (const float*)d_in[2];
    float* o       = (float*)d_out;

    cudaFuncSetAttribute(swa_kernel, cudaFuncAttributeMaxDynamicSharedMemorySize, SMEM_BYTES);
    // grid: 2 batches * 64 tiles = 128 CTAs (one wave on 148 SMs)
    swa_kernel<<<128, THREADS, SMEM_BYTES>>>(q, k, v, o);
}